// round 9
// baseline (speedup 1.0000x reference)
#include <cuda_runtime.h>
#include <cstdint>

// Per-slot global accumulators + ticket (zero at module load; last block
// resets -> clean each launch/graph replay; integer atomics -> exact).
#define NSLOTS 32
#define SLOT_STRIDE 32
__device__ unsigned int g_slots[NSLOTS * SLOT_STRIDE];
__device__ unsigned int g_ticket;

// Packed counters: bits [0:10)=label1, [10:20)=label2, [20:30)=label3.
// Max per-thread per-label count = 432 < 1023 -> exact, no overflow.
#define LANE(x, y) do {                                                   \
    unsigned int m1 = ((x) == 1.0f), m2 = ((x) == 2.0f), m3 = ((x) == 3.0f); \
    unsigned int n1 = ((y) == 1.0f), n2 = ((y) == 2.0f), n3 = ((y) == 3.0f); \
    pa += m1 + (m2 << 10) + (m3 << 20);                                   \
    pb += n1 + (n2 << 10) + (n3 << 20);                                   \
    pi += (m1 & n1) + ((m2 & n2) << 10) + ((m3 & n3) << 20);              \
} while (0)

__global__ void __launch_bounds__(256, 8) dice_fused_kernel(
    const float4* __restrict__ a, const float4* __restrict__ b,
    int half_vec, float* __restrict__ out)
{
    unsigned int pa = 0, pb = 0, pi = 0;

    const int stride = gridDim.x * blockDim.x;
    const float4* __restrict__ ah = a + half_vec;
    const float4* __restrict__ bh = b + half_vec;

    // Two independent streams per thread: 4 front-batched LDG.128 per
    // iteration -> MLP/warp ~4 (vs ~2), enough in-flight bytes to cover
    // DRAM latency at the 64 B/cyc/SM demand rate.
    for (int idx = blockIdx.x * blockDim.x + threadIdx.x;
         idx < half_vec; idx += stride) {
        float4 va0 = __ldcs(&a [idx]);
        float4 vb0 = __ldcs(&b [idx]);
        float4 va1 = __ldcs(&ah[idx]);
        float4 vb1 = __ldcs(&bh[idx]);

        LANE(va0.x, vb0.x); LANE(va0.y, vb0.y);
        LANE(va0.z, vb0.z); LANE(va0.w, vb0.w);
        LANE(va1.x, vb1.x); LANE(va1.y, vb1.y);
        LANE(va1.z, vb1.z); LANE(va1.w, vb1.w);
    }

    // unpack packed fields -> 9 counters (must unpack before cross-lane sum)
    unsigned int v[9];
    v[0] = pa & 1023u; v[1] = (pa >> 10) & 1023u; v[2] = (pa >> 20) & 1023u;
    v[3] = pb & 1023u; v[4] = (pb >> 10) & 1023u; v[5] = (pb >> 20) & 1023u;
    v[6] = pi & 1023u; v[7] = (pi >> 10) & 1023u; v[8] = (pi >> 20) & 1023u;

    #pragma unroll
    for (int k = 0; k < 9; ++k) {
        #pragma unroll
        for (int off = 16; off > 0; off >>= 1)
            v[k] += __shfl_down_sync(0xFFFFFFFFu, v[k], off);
    }

    // block reduce via shared atomics
    __shared__ unsigned int s[9];
    __shared__ bool is_last;
    if (threadIdx.x < 9) s[threadIdx.x] = 0u;
    __syncthreads();
    if ((threadIdx.x & 31) == 0) {
        #pragma unroll
        for (int k = 0; k < 9; ++k) atomicAdd(&s[k], v[k]);
    }
    __syncthreads();

    // global accumulate into this block's slot, then ticket
    const unsigned int slot = (blockIdx.x & (NSLOTS - 1)) * SLOT_STRIDE;
    if (threadIdx.x < 9)
        atomicAdd(&g_slots[slot + threadIdx.x], s[threadIdx.x]);
    __threadfence();
    if (threadIdx.x == 0) {
        unsigned int t = atomicAdd(&g_ticket, 1u);
        is_last = (t == gridDim.x - 1u);
    }
    __syncthreads();

    if (is_last) {
        __threadfence();
        __shared__ unsigned int tot_s[9];
        if (threadIdx.x < 9) {
            unsigned int t = 0;
            #pragma unroll
            for (int sl = 0; sl < NSLOTS; ++sl)
                t += g_slots[sl * SLOT_STRIDE + threadIdx.x];
            tot_s[threadIdx.x] = t;
        }
        __syncthreads();

        if (threadIdx.x == 0) {
            const float eps = 1.1920928955078125e-07f;  // np.finfo(float32).eps
            float sum = 0.0f;
            #pragma unroll
            for (int l = 0; l < 3; ++l) {
                float inter = (float)tot_s[6 + l];
                float bot   = (float)tot_s[l] + (float)tot_s[3 + l];
                sum += (2.0f * inter) / (bot + eps);
            }
            out[0] = 1.0f - sum * (1.0f / 3.0f);
        }

        // reset for next launch / graph replay
        for (int k = threadIdx.x; k < NSLOTS * SLOT_STRIDE; k += blockDim.x)
            g_slots[k] = 0u;
        __syncthreads();
        if (threadIdx.x == 0) {
            __threadfence();
            g_ticket = 0u;
        }
    }
}

extern "C" void kernel_launch(void* const* d_in, const int* in_sizes, int n_in,
                              void* d_out, int out_size)
{
    const float4* a = (const float4*)d_in[0];
    const float4* b = (const float4*)d_in[1];
    float* out = (float*)d_out;

    int n = in_sizes[0];        // 512^3, divisible by 8
    int n_vec    = n >> 2;      // float4 count (2^25)
    int half_vec = n_vec >> 1;  // 2^24

    const int threads = 256;
    const int blocks  = 152 * 8;   // 1216
    dice_fused_kernel<<<blocks, threads>>>(a, b, half_vec, out);
}

// round 10
// speedup vs baseline: 1.0960x; 1.0960x over previous
#include <cuda_runtime.h>
#include <cstdint>

// Per-block partials, overwritten unconditionally every launch (no zeroing,
// no atomics, no fences -> no device state carried across launches).
// Layout g_partials[k * MAX_BLOCKS + blockIdx] for coalesced finalize reads.
#define MAX_BLOCKS 1280
__device__ unsigned int g_partials[9 * MAX_BLOCKS];

__device__ __forceinline__ void accum_lane(float x, float y,
    unsigned int& c0, unsigned int& c1, unsigned int& c2,
    unsigned int& d0, unsigned int& d1, unsigned int& d2,
    unsigned int& i0, unsigned int& i1, unsigned int& i2)
{
    bool m1 = (x == 1.0f), m2 = (x == 2.0f), m3 = (x == 3.0f);
    bool n1 = (y == 1.0f), n2 = (y == 2.0f), n3 = (y == 3.0f);
    c0 += m1; c1 += m2; c2 += m3;
    d0 += n1; d1 += n2; d2 += n3;
    i0 += (m1 & n1); i1 += (m2 & n2); i2 += (m3 & n3);
}

__global__ void __launch_bounds__(256, 8) dice_count_kernel(
    const float4* __restrict__ a, const float4* __restrict__ b, int n_vec)
{
    unsigned int c0 = 0, c1 = 0, c2 = 0;
    unsigned int d0 = 0, d1 = 0, d2 = 0;
    unsigned int i0 = 0, i1 = 0, i2 = 0;

    const int stride = gridDim.x * blockDim.x;
    int idx = blockIdx.x * blockDim.x + threadIdx.x;

    #pragma unroll 8
    for (; idx < n_vec; idx += stride) {
        float4 va = __ldcs(&a[idx]);
        float4 vb = __ldcs(&b[idx]);
        accum_lane(va.x, vb.x, c0,c1,c2, d0,d1,d2, i0,i1,i2);
        accum_lane(va.y, vb.y, c0,c1,c2, d0,d1,d2, i0,i1,i2);
        accum_lane(va.z, vb.z, c0,c1,c2, d0,d1,d2, i0,i1,i2);
        accum_lane(va.w, vb.w, c0,c1,c2, d0,d1,d2, i0,i1,i2);
    }

    // warp reduce 9 counters
    unsigned int v[9] = {c0, c1, c2, d0, d1, d2, i0, i1, i2};
    #pragma unroll
    for (int k = 0; k < 9; ++k) {
        #pragma unroll
        for (int off = 16; off > 0; off >>= 1)
            v[k] += __shfl_down_sync(0xFFFFFFFFu, v[k], off);
    }

    // block reduce via shared atomics, then 9 plain STGs. No fence, no
    // global atomic: kernel boundary provides ordering for the finalize.
    __shared__ unsigned int s[9];
    if (threadIdx.x < 9) s[threadIdx.x] = 0u;
    __syncthreads();
    if ((threadIdx.x & 31) == 0) {
        #pragma unroll
        for (int k = 0; k < 9; ++k) atomicAdd(&s[k], v[k]);
    }
    __syncthreads();
    if (threadIdx.x < 9)
        g_partials[threadIdx.x * MAX_BLOCKS + blockIdx.x] = s[threadIdx.x];
}

// 9 warps: warp k reduces counter k over n_blocks partials (coalesced
// strided loads, all independent -> fully pipelined), then thread 0 computes.
__global__ void __launch_bounds__(288) dice_final_kernel(
    float* __restrict__ out, int n_blocks)
{
    __shared__ unsigned int tot_s[9];
    const int w   = threadIdx.x >> 5;   // 0..8
    const int ln  = threadIdx.x & 31;

    unsigned int sum = 0;
    for (int i = ln; i < n_blocks; i += 32)
        sum += g_partials[w * MAX_BLOCKS + i];
    #pragma unroll
    for (int off = 16; off > 0; off >>= 1)
        sum += __shfl_down_sync(0xFFFFFFFFu, sum, off);
    if (ln == 0) tot_s[w] = sum;
    __syncthreads();

    if (threadIdx.x == 0) {
        const float eps = 1.1920928955078125e-07f;  // np.finfo(float32).eps
        float acc = 0.0f;
        #pragma unroll
        for (int l = 0; l < 3; ++l) {
            float inter = (float)tot_s[6 + l];
            float bot   = (float)tot_s[l] + (float)tot_s[3 + l];
            acc += (2.0f * inter) / (bot + eps);
        }
        out[0] = 1.0f - acc * (1.0f / 3.0f);
    }
}

extern "C" void kernel_launch(void* const* d_in, const int* in_sizes, int n_in,
                              void* d_out, int out_size)
{
    const float4* a = (const float4*)d_in[0];
    const float4* b = (const float4*)d_in[1];
    float* out = (float*)d_out;

    int n = in_sizes[0];        // 512^3, divisible by 4
    int n_vec = n >> 2;

    const int threads = 256;
    const int blocks  = 152 * 8;   // 1216 <= MAX_BLOCKS
    dice_count_kernel<<<blocks, threads>>>(a, b, n_vec);
    dice_final_kernel<<<1, 288>>>(out, blocks);
}

// round 11
// speedup vs baseline: 1.1050x; 1.0082x over previous
#include <cuda_runtime.h>
#include <cstdint>

// Per-block partials, overwritten unconditionally every launch (no zeroing,
// no atomics, no fences, no persistent state).
// Layout g_partials[k * MAX_BLOCKS + blockIdx] for coalesced finalize reads.
#define MAX_BLOCKS 1280
__device__ unsigned int g_partials[9 * MAX_BLOCKS];

__device__ __forceinline__ void accum_lane(float x, float y,
    unsigned int& c0, unsigned int& c1, unsigned int& c2,
    unsigned int& d0, unsigned int& d1, unsigned int& d2,
    unsigned int& i0, unsigned int& i1, unsigned int& i2)
{
    bool m1 = (x == 1.0f), m2 = (x == 2.0f), m3 = (x == 3.0f);
    bool n1 = (y == 1.0f), n2 = (y == 2.0f), n3 = (y == 3.0f);
    c0 += m1; c1 += m2; c2 += m3;
    d0 += n1; d1 += n2; d2 += n3;
    i0 += (m1 & n1); i1 += (m2 & n2); i2 += (m3 & n3);
}

__global__ void __launch_bounds__(256, 8) dice_count_kernel(
    const float4* __restrict__ a, const float4* __restrict__ b, int n_vec)
{
    unsigned int c0 = 0, c1 = 0, c2 = 0;
    unsigned int d0 = 0, d1 = 0, d2 = 0;
    unsigned int i0 = 0, i1 = 0, i2 = 0;

    const int stride = gridDim.x * blockDim.x;
    int idx = blockIdx.x * blockDim.x + threadIdx.x;

    #pragma unroll 8
    for (; idx < n_vec; idx += stride) {
        float4 va = __ldcs(&a[idx]);
        float4 vb = __ldcs(&b[idx]);
        accum_lane(va.x, vb.x, c0,c1,c2, d0,d1,d2, i0,i1,i2);
        accum_lane(va.y, vb.y, c0,c1,c2, d0,d1,d2, i0,i1,i2);
        accum_lane(va.z, vb.z, c0,c1,c2, d0,d1,d2, i0,i1,i2);
        accum_lane(va.w, vb.w, c0,c1,c2, d0,d1,d2, i0,i1,i2);
    }

    // PDL trigger: allow the finalize kernel to be scheduled now. Purely a
    // scheduling hint; the finalize's griddepcontrol.wait still blocks until
    // THIS grid's memory is fully visible.
    asm volatile("griddepcontrol.launch_dependents;");

    // warp reduce 9 counters
    unsigned int v[9] = {c0, c1, c2, d0, d1, d2, i0, i1, i2};
    #pragma unroll
    for (int k = 0; k < 9; ++k) {
        #pragma unroll
        for (int off = 16; off > 0; off >>= 1)
            v[k] += __shfl_down_sync(0xFFFFFFFFu, v[k], off);
    }

    // block reduce via shared atomics, then 9 plain STGs (kernel-boundary /
    // PDL-wait ordering; no fence, no global atomics).
    __shared__ unsigned int s[9];
    if (threadIdx.x < 9) s[threadIdx.x] = 0u;
    __syncthreads();
    if ((threadIdx.x & 31) == 0) {
        #pragma unroll
        for (int k = 0; k < 9; ++k) atomicAdd(&s[k], v[k]);
    }
    __syncthreads();
    if (threadIdx.x < 9)
        g_partials[threadIdx.x * MAX_BLOCKS + blockIdx.x] = s[threadIdx.x];
}

// 9 warps: warp k reduces counter k over n_blocks partials.
__global__ void __launch_bounds__(288) dice_final_kernel(
    float* __restrict__ out, int n_blocks)
{
    // Block until the count grid's writes are visible (PDL).
    asm volatile("griddepcontrol.wait;");

    __shared__ unsigned int tot_s[9];
    const int w  = threadIdx.x >> 5;   // 0..8
    const int ln = threadIdx.x & 31;

    unsigned int sum = 0;
    for (int i = ln; i < n_blocks; i += 32)
        sum += g_partials[w * MAX_BLOCKS + i];
    #pragma unroll
    for (int off = 16; off > 0; off >>= 1)
        sum += __shfl_down_sync(0xFFFFFFFFu, sum, off);
    if (ln == 0) tot_s[w] = sum;
    __syncthreads();

    if (threadIdx.x == 0) {
        const float eps = 1.1920928955078125e-07f;  // np.finfo(float32).eps
        float acc = 0.0f;
        #pragma unroll
        for (int l = 0; l < 3; ++l) {
            float inter = (float)tot_s[6 + l];
            float bot   = (float)tot_s[l] + (float)tot_s[3 + l];
            acc += (2.0f * inter) / (bot + eps);
        }
        out[0] = 1.0f - acc * (1.0f / 3.0f);
    }
}

extern "C" void kernel_launch(void* const* d_in, const int* in_sizes, int n_in,
                              void* d_out, int out_size)
{
    const float4* a = (const float4*)d_in[0];
    const float4* b = (const float4*)d_in[1];
    float* out = (float*)d_out;

    int n = in_sizes[0];        // 512^3, divisible by 4
    int n_vec = n >> 2;

    const int threads = 256;
    const int blocks  = 152 * 8;   // 1216 <= MAX_BLOCKS
    dice_count_kernel<<<blocks, threads>>>(a, b, n_vec);

    // Finalize with programmatic dependent launch: overlaps its launch/ramp
    // with the count kernel's drain; it self-synchronizes via
    // griddepcontrol.wait.
    cudaLaunchConfig_t cfg = {};
    cfg.gridDim  = dim3(1, 1, 1);
    cfg.blockDim = dim3(288, 1, 1);
    cfg.dynamicSmemBytes = 0;
    cfg.stream = 0;
    cudaLaunchAttribute attr;
    attr.id = cudaLaunchAttributeProgrammaticStreamSerialization;
    attr.val.programmaticStreamSerializationAllowed = 1;
    cfg.attrs = &attr;
    cfg.numAttrs = 1;
    cudaLaunchKernelEx(&cfg, dice_final_kernel, out, blocks);
}

// round 12
// speedup vs baseline: 1.1279x; 1.0207x over previous
#include <cuda_runtime.h>
#include <cstdint>

// Per-slot global accumulators + ticket (zero at module load; last block
// resets -> clean each launch/graph replay; integer atomics -> exact).
// Slots hold MOMENTS: [0..2]=S1..S3 of vol1, [3..5]=vol2, [6..8]=diag(d).
#define NSLOTS 32
#define SLOT_STRIDE 32
__device__ unsigned int g_slots[NSLOTS * SLOT_STRIDE];
__device__ unsigned int g_ticket;

// Moment accumulation: 14 instr per element pair (vs 18 for direct counting),
// shifted onto the FMA pipe. All values are small integers -> fp32 exact.
#define LANE(x, y) do {                                   \
    float tx = (x) * (x);                                 \
    sa1 += (x);  sa2 += tx;  sa3 = fmaf(tx, (x), sa3);    \
    float ty = (y) * (y);                                 \
    sb1 += (y);  sb2 += ty;  sb3 = fmaf(ty, (y), sb3);    \
    float d  = ((x) == (y)) ? (x) : 0.0f;                 \
    float td = d * d;                                     \
    si1 += d;    si2 += td;  si3 = fmaf(td, d, si3);      \
} while (0)

__global__ void __launch_bounds__(256, 8) dice_fused_kernel(
    const float4* __restrict__ a, const float4* __restrict__ b,
    int n_vec, float* __restrict__ out)
{
    float sa1 = 0.f, sa2 = 0.f, sa3 = 0.f;
    float sb1 = 0.f, sb2 = 0.f, sb3 = 0.f;
    float si1 = 0.f, si2 = 0.f, si3 = 0.f;

    const int stride = gridDim.x * blockDim.x;
    int idx = blockIdx.x * blockDim.x + threadIdx.x;

    #pragma unroll 8
    for (; idx < n_vec; idx += stride) {
        float4 va = __ldcs(&a[idx]);
        float4 vb = __ldcs(&b[idx]);
        LANE(va.x, vb.x);
        LANE(va.y, vb.y);
        LANE(va.z, vb.z);
        LANE(va.w, vb.w);
    }

    // warp reduce 9 float moments (exact: integer-valued, < 2^24 throughout)
    float v[9] = {sa1, sa2, sa3, sb1, sb2, sb3, si1, si2, si3};
    #pragma unroll
    for (int k = 0; k < 9; ++k) {
        #pragma unroll
        for (int off = 16; off > 0; off >>= 1)
            v[k] += __shfl_down_sync(0xFFFFFFFFu, v[k], off);
    }

    // block reduce: warp leaders -> shared, warp 0 lanes 0..8 finish.
    __shared__ float ws[8][9];
    __shared__ bool is_last;
    if ((threadIdx.x & 31) == 0) {
        #pragma unroll
        for (int k = 0; k < 9; ++k) ws[threadIdx.x >> 5][k] = v[k];
    }
    __syncthreads();

    const unsigned int slot = (blockIdx.x & (NSLOTS - 1)) * SLOT_STRIDE;
    if (threadIdx.x < 9) {
        float t = 0.f;
        #pragma unroll
        for (int w = 0; w < 8; ++w) t += ws[w][threadIdx.x];
        // exact integer in fp32 -> exact uint conversion
        atomicAdd(&g_slots[slot + threadIdx.x], (unsigned int)t);
    }
    __threadfence();
    if (threadIdx.x == 0) {
        unsigned int t = atomicAdd(&g_ticket, 1u);
        is_last = (t == gridDim.x - 1u);
    }
    __syncthreads();

    if (is_last) {
        __threadfence();
        __shared__ unsigned int tot_s[9];
        if (threadIdx.x < 9) {
            unsigned int t = 0;
            #pragma unroll
            for (int sl = 0; sl < NSLOTS; ++sl)
                t += g_slots[sl * SLOT_STRIDE + threadIdx.x];
            tot_s[threadIdx.x] = t;
        }
        __syncthreads();

        if (threadIdx.x == 0) {
            // Recover counts from moments (labels 1,2,3; exact int64 math):
            //   m1 = c1 + 2c2 + 3c3 ; m2 = c1 + 4c2 + 9c3 ; m3 = c1 + 8c2 + 27c3
            //   c3 = (m3 - 3m2 + 2m1)/6 ; c2 = (m2 - m1 - 6c3)/2 ; c1 = m1 - 2c2 - 3c3
            long long cnt[9];
            #pragma unroll
            for (int g = 0; g < 3; ++g) {
                long long m1 = (long long)tot_s[g * 3 + 0];
                long long m2 = (long long)tot_s[g * 3 + 1];
                long long m3 = (long long)tot_s[g * 3 + 2];
                long long c3 = (m3 - 3 * m2 + 2 * m1) / 6;
                long long c2 = (m2 - m1 - 6 * c3) / 2;
                long long c1 = m1 - 2 * c2 - 3 * c3;
                cnt[g * 3 + 0] = c1; cnt[g * 3 + 1] = c2; cnt[g * 3 + 2] = c3;
            }

            const float eps = 1.1920928955078125e-07f;  // np.finfo(float32).eps
            float sum = 0.0f;
            #pragma unroll
            for (int l = 0; l < 3; ++l) {
                float inter = (float)cnt[6 + l];           // intersection
                float bot   = (float)cnt[l] + (float)cnt[3 + l];
                sum += (2.0f * inter) / (bot + eps);
            }
            out[0] = 1.0f - sum * (1.0f / 3.0f);
        }

        // reset for next launch / graph replay
        for (int k = threadIdx.x; k < NSLOTS * SLOT_STRIDE; k += blockDim.x)
            g_slots[k] = 0u;
        __syncthreads();
        if (threadIdx.x == 0) {
            __threadfence();
            g_ticket = 0u;
        }
    }
}

extern "C" void kernel_launch(void* const* d_in, const int* in_sizes, int n_in,
                              void* d_out, int out_size)
{
    const float4* a = (const float4*)d_in[0];
    const float4* b = (const float4*)d_in[1];
    float* out = (float*)d_out;

    int n = in_sizes[0];        // 512^3, divisible by 4
    int n_vec = n >> 2;

    const int threads = 256;
    const int blocks  = 152 * 8;   // 1216
    dice_fused_kernel<<<blocks, threads>>>(a, b, n_vec, out);
}

// round 13
// speedup vs baseline: 1.1281x; 1.0002x over previous
#include <cuda_runtime.h>
#include <cstdint>

// 9 global moment accumulators + ticket. Zero at module load; the last block
// resets them each launch -> clean state for every graph replay. Integer
// atomics on exact integer-valued data -> deterministic.
__device__ unsigned int g_counts[9];
__device__ unsigned int g_ticket;

// Moment accumulation (R12, proven): labels are exact small ints in fp32, so
// sums stay exact (< 2^24 per block). FMA-pipe heavy; issue ~37%.
#define LANE(x, y) do {                                   \
    float tx = (x) * (x);                                 \
    sa1 += (x);  sa2 += tx;  sa3 = fmaf(tx, (x), sa3);    \
    float ty = (y) * (y);                                 \
    sb1 += (y);  sb2 += ty;  sb3 = fmaf(ty, (y), sb3);    \
    float d  = ((x) == (y)) ? (x) : 0.0f;                 \
    float td = d * d;                                     \
    si1 += d;    si2 += td;  si3 = fmaf(td, d, si3);      \
} while (0)

__global__ void __launch_bounds__(256, 8) dice_fused_kernel(
    const float4* __restrict__ a, const float4* __restrict__ b,
    int n_vec, float* __restrict__ out)
{
    float sa1 = 0.f, sa2 = 0.f, sa3 = 0.f;
    float sb1 = 0.f, sb2 = 0.f, sb3 = 0.f;
    float si1 = 0.f, si2 = 0.f, si3 = 0.f;

    const int stride = gridDim.x * blockDim.x;
    int idx = blockIdx.x * blockDim.x + threadIdx.x;

    #pragma unroll 8
    for (; idx < n_vec; idx += stride) {
        float4 va = __ldcs(&a[idx]);
        float4 vb = __ldcs(&b[idx]);
        LANE(va.x, vb.x);
        LANE(va.y, vb.y);
        LANE(va.z, vb.z);
        LANE(va.w, vb.w);
    }

    // warp reduce 9 float moments (exact integers throughout)
    float v[9] = {sa1, sa2, sa3, sb1, sb2, sb3, si1, si2, si3};
    #pragma unroll
    for (int k = 0; k < 9; ++k) {
        #pragma unroll
        for (int off = 16; off > 0; off >>= 1)
            v[k] += __shfl_down_sync(0xFFFFFFFFu, v[k], off);
    }

    // block reduce: warp leaders -> shared, lanes 0..8 of the block finish
    __shared__ float ws[8][9];
    __shared__ bool is_last;
    if ((threadIdx.x & 31) == 0) {
        #pragma unroll
        for (int k = 0; k < 9; ++k) ws[threadIdx.x >> 5][k] = v[k];
    }
    __syncthreads();

    if (threadIdx.x < 9) {
        float t = 0.f;
        #pragma unroll
        for (int w = 0; w < 8; ++w) t += ws[w][threadIdx.x];
        atomicAdd(&g_counts[threadIdx.x], (unsigned int)t);  // exact
    }
    __threadfence();
    if (threadIdx.x == 0) {
        unsigned int t = atomicAdd(&g_ticket, 1u);
        is_last = (t == gridDim.x - 1u);
    }
    __syncthreads();

    if (is_last && threadIdx.x == 0) {
        __threadfence();
        unsigned int tot[9];
        #pragma unroll
        for (int k = 0; k < 9; ++k) tot[k] = atomicAdd(&g_counts[k], 0u);

        // Recover counts from moments (labels 1,2,3; exact int64 math):
        //   m1 = c1 + 2c2 + 3c3 ; m2 = c1 + 4c2 + 9c3 ; m3 = c1 + 8c2 + 27c3
        long long cnt[9];
        #pragma unroll
        for (int g = 0; g < 3; ++g) {
            long long m1 = (long long)tot[g * 3 + 0];
            long long m2 = (long long)tot[g * 3 + 1];
            long long m3 = (long long)tot[g * 3 + 2];
            long long c3 = (m3 - 3 * m2 + 2 * m1) / 6;
            long long c2 = (m2 - m1 - 6 * c3) / 2;
            long long c1 = m1 - 2 * c2 - 3 * c3;
            cnt[g * 3 + 0] = c1; cnt[g * 3 + 1] = c2; cnt[g * 3 + 2] = c3;
        }

        const float eps = 1.1920928955078125e-07f;  // np.finfo(float32).eps
        float sum = 0.0f;
        #pragma unroll
        for (int l = 0; l < 3; ++l) {
            float inter = (float)cnt[6 + l];
            float bot   = (float)cnt[l] + (float)cnt[3 + l];
            sum += (2.0f * inter) / (bot + eps);
        }
        out[0] = 1.0f - sum * (1.0f / 3.0f);

        // reset: just 9 words + ticket
        #pragma unroll
        for (int k = 0; k < 9; ++k) g_counts[k] = 0u;
        __threadfence();
        g_ticket = 0u;
    }
}

extern "C" void kernel_launch(void* const* d_in, const int* in_sizes, int n_in,
                              void* d_out, int out_size)
{
    const float4* a = (const float4*)d_in[0];
    const float4* b = (const float4*)d_in[1];
    float* out = (float*)d_out;

    int n = in_sizes[0];        // 512^3, divisible by 4
    int n_vec = n >> 2;

    const int threads = 256;
    const int blocks  = 152 * 8;   // 1216
    dice_fused_kernel<<<blocks, threads>>>(a, b, n_vec, out);
}